// round 3
// baseline (speedup 1.0000x reference)
#include <cuda_runtime.h>
#include <cuda_bf16.h>
#include <math.h>

// Problem constants
#define BATCH   64
#define NF      256
#define WIN     128
#define EMB     128
#define TOPK    32
#define ALPHA   0.2f

#define NBLK      2048          // total blocks (attn: 8 warps each)
#define GEMM_BLK  256           // blocks that also produce a GEMM tile (64 rows)

// Scratch
__device__ float    g_Wx[BATCH * NF * EMB];   // Wx = x_n @ W_n + b_n (8.4 MB)
__device__ float    g_d1[BATCH * NF];         // dot(Wx[b,r], a[:128])
__device__ float    g_d2[BATCH * NF];         // dot(Wx[b,r], a[128:])
__device__ unsigned g_flag[BATCH];            // per-batch tiles-done counter (0..4)
__device__ unsigned g_done;                   // blocks-finished counter (self-reset)

__device__ __forceinline__ float lrelu(float v) {
    return fmaxf(v, ALPHA * v);   // valid for alpha in (0,1)
}

// ---------------------------------------------------------------------------
// Fused kernel.
//  Phase A (blocks 0..255): GEMM tile of 64 rows:
//      Wx[r][e] = sum_w x[r][w]*W[w][e] + b[e];  d1[r]=Wx[r]·a1; d2[r]=Wx[r]·a2
//      then release flag[batch-of-tile].
//  Phase B (all blocks): spin until flag[my batch]==4, then per warp (b,n):
//      score_k = lrelu(k<16 ? d1[n]+d2[n] : d1[nbr(2k-32)]+d2[nbr(2k-31)])
//                + nan_to_num(bias[n,k]);  warp softmax -> att
//      out[b,n,k,:] = att_k * lrelu(Wx[b,nbr[n,k]])   (att>0 commutes w/ lrelu)
//  Phase C: last block resets flags + done counter (graph-replay safe).
// ---------------------------------------------------------------------------
__global__ __launch_bounds__(256) void fused_kernel(
    const float* __restrict__ x,     // [BATCH*NF, WIN]
    const float* __restrict__ Wn,    // [WIN, EMB]
    const float* __restrict__ bn,    // [EMB]
    const float* __restrict__ a,     // [2*EMB]
    const int*   __restrict__ edge,  // [2, NF*TOPK] (row 0 used)
    const float* __restrict__ bias,  // [NF, TOPK]
    float*       __restrict__ out)   // [BATCH, NF, TOPK, EMB]
{
    __shared__ float sX[32][65];     // [k][m], padded
    __shared__ float sW[32][128];    // [k][e]

    const int t   = threadIdx.x;
    const int bid = blockIdx.x;

    // ---------------- Phase A: GEMM producers ----------------
    if (bid < GEMM_BLK) {
        const int row0 = bid * 64;
        const int tx   = t & 15;     // e-direction
        const int ty   = t >> 4;     // m-direction

        float acc[4][8];
#pragma unroll
        for (int i = 0; i < 4; i++)
#pragma unroll
            for (int j = 0; j < 8; j++) acc[i][j] = 0.0f;

        for (int kt = 0; kt < WIN; kt += 32) {
#pragma unroll
            for (int i = 0; i < 8; i++) {
                int idx = t + i * 256;
                int m = idx >> 5, w = idx & 31;
                sX[w][m] = x[(size_t)(row0 + m) * WIN + kt + w];
            }
#pragma unroll
            for (int i = 0; i < 16; i++) {
                int idx = t + i * 256;
                int kk = idx >> 7, e = idx & 127;
                sW[kk][e] = Wn[(size_t)(kt + kk) * EMB + e];
            }
            __syncthreads();

#pragma unroll
            for (int kk = 0; kk < 32; kk++) {
                float ra[4], rb[8];
#pragma unroll
                for (int i = 0; i < 4; i++) ra[i] = sX[kk][ty + 16 * i];
#pragma unroll
                for (int j = 0; j < 8; j++) rb[j] = sW[kk][tx + 16 * j];
#pragma unroll
                for (int i = 0; i < 4; i++)
#pragma unroll
                    for (int j = 0; j < 8; j++)
                        acc[i][j] = fmaf(ra[i], rb[j], acc[i][j]);
            }
            __syncthreads();
        }

        // Epilogue: bias, store Wx, fused projections d1/d2
        float a1v[8], a2v[8], bnv[8];
#pragma unroll
        for (int j = 0; j < 8; j++) {
            int e = tx + 16 * j;
            a1v[j] = __ldg(a + e);
            a2v[j] = __ldg(a + EMB + e);
            bnv[j] = __ldg(bn + e);
        }
        float p1[4] = {0, 0, 0, 0};
        float p2[4] = {0, 0, 0, 0};
#pragma unroll
        for (int i = 0; i < 4; i++) {
            int m = row0 + ty + 16 * i;
#pragma unroll
            for (int j = 0; j < 8; j++) {
                int e = tx + 16 * j;
                float val = acc[i][j] + bnv[j];
                g_Wx[(size_t)m * EMB + e] = val;
                p1[i] = fmaf(val, a1v[j], p1[i]);
                p2[i] = fmaf(val, a2v[j], p2[i]);
            }
        }
#pragma unroll
        for (int i = 0; i < 4; i++) {
#pragma unroll
            for (int o = 8; o > 0; o >>= 1) {
                p1[i] += __shfl_xor_sync(0xffffffffu, p1[i], o);
                p2[i] += __shfl_xor_sync(0xffffffffu, p2[i], o);
            }
        }
        if (tx == 0) {
#pragma unroll
            for (int i = 0; i < 4; i++) {
                int m = row0 + ty + 16 * i;
                g_d1[m] = p1[i];
                g_d2[m] = p2[i];
            }
        }

        // Release: all block stores done -> fence -> bump batch flag
        __syncthreads();
        if (t == 0) {
            __threadfence();
            atomicAdd(&g_flag[bid >> 2], 1u);   // tile's batch = rows/256 = bid/4
        }
    }

    // ---------------- Phase B: attention consumers ----------------
    const int wid = t >> 5;
    const int l   = t & 31;
    const int gw  = bid * 8 + wid;        // 0..16383 = (b,n) pair
    const int b   = gw >> 8;              // all 8 warps of a block share b
    const int n   = gw & 255;

    // Wait until batch b's 4 GEMM tiles are published
    if (t == 0) {
        volatile unsigned* f = &g_flag[b];
        while (*f < 4u) { }
        __threadfence();                   // acquire
    }
    __syncthreads();

    const float* d1 = g_d1 + b * NF;
    const float* d2 = g_d2 + b * NF;

    const int nbr_l = __ldg(edge + n * TOPK + l);

    float score;
    if (l < 16) {
        score = lrelu(d1[n] + d2[n]);
    } else {
        int j0 = 2 * l - 32;
        int n0 = __ldg(edge + n * TOPK + j0);
        int n1 = __ldg(edge + n * TOPK + j0 + 1);
        score = lrelu(d1[n0] + d2[n1]);
    }
    float bv = __ldg(bias + n * TOPK + l);
    if (isnan(bv)) bv = 0.0f;
    else if (isinf(bv)) bv = bv > 0.0f ? 3.4028235e38f : -3.4028235e38f;
    score += bv;

    // Warp softmax over 32 lanes
    float m = score;
#pragma unroll
    for (int o = 16; o > 0; o >>= 1) m = fmaxf(m, __shfl_xor_sync(0xffffffffu, m, o));
    float ex = __expf(score - m);
    float s = ex;
#pragma unroll
    for (int o = 16; o > 0; o >>= 1) s += __shfl_xor_sync(0xffffffffu, s, o);
    const float att = ex / s;

    // Streaming output: 32 rows x 32 float4
    const float* wxb = g_Wx + (size_t)b * NF * EMB;
    float4* outp = (float4*)(out + (size_t)gw * TOPK * EMB);

#pragma unroll 8
    for (int k = 0; k < TOPK; k++) {
        int   nb = __shfl_sync(0xffffffffu, nbr_l, k);
        float ak = __shfl_sync(0xffffffffu, att,   k);
        const float4* src = (const float4*)(wxb + (size_t)nb * EMB);
        float4 v = __ldg(src + l);
        v.x = lrelu(v.x) * ak;
        v.y = lrelu(v.y) * ak;
        v.z = lrelu(v.z) * ak;
        v.w = lrelu(v.w) * ak;
        __stcs(outp + k * 32 + l, v);
    }

    // ---------------- Phase C: self-reset for graph replay ----------------
    __syncthreads();
    if (t == 0) {
        unsigned v = atomicAdd(&g_done, 1u);
        if (v == NBLK - 1u) {
            // All blocks have passed their flag reads; safe to reset.
#pragma unroll
            for (int i = 0; i < BATCH; i++) g_flag[i] = 0u;
            g_done = 0u;
            __threadfence();
        }
    }
}

// ---------------------------------------------------------------------------
// Launch. Inputs: 0:x_n 1:x_e 2:edge_indices 3:all_embeddings 4:W_n 5:b_n
//                 6:a 7:bias_n   (x_e, all_embeddings unused)
// ---------------------------------------------------------------------------
extern "C" void kernel_launch(void* const* d_in, const int* in_sizes, int n_in,
                              void* d_out, int out_size) {
    const float* x_n  = (const float*)d_in[0];
    const int*   edge = (const int*)  d_in[2];
    const float* W_n  = (const float*)d_in[4];
    const float* b_n  = (const float*)d_in[5];
    const float* a    = (const float*)d_in[6];
    const float* bias = (const float*)d_in[7];
    float* out = (float*)d_out;

    fused_kernel<<<NBLK, 256>>>(x_n, W_n, b_n, a, edge, bias, out);
}